// round 5
// baseline (speedup 1.0000x reference)
#include <cuda_runtime.h>
#include <cuda_bf16.h>
#include <cstdint>

// ============================================================================
// Policy_Network via mma.sync bf16 split-GEMM (legacy HMMA path; tcgen05 is
// unavailable: harness PTX targets plain sm_103, no 'a' features).
//   ctx = [state|task|action] -> [8192, 5124] padded to 5152
//   x1 = ctx @ W1 + b1   [8192,2048]
//   x2 = [x1|ctx] @ W2   [8192,1024]
//   x3 = [x2|ctx] @ W3   [8192,1024]
//   x4 = [x3|ctx] @ W4   [8192,512]
//   out= x4 @ W5 + b5    [8192,1024] fp32
// fp32 a = a_hi + a_lo (bf16); product = ah*bh + ah*bl + al*bh in fp32 acc.
// R5: 3-stage cp.async pipeline with FIXED stage-rotation index (R4 bug).
// ============================================================================

#define BATCH   8192
#define CTXP    5152            // 5124 padded to 32

typedef __nv_bfloat16 bf16;

// ---------------- device scratch (no allocation allowed) -------------------
__device__ bf16 g_ctx_h[(size_t)BATCH * CTXP];
__device__ bf16 g_ctx_l[(size_t)BATCH * CTXP];
__device__ bf16 g_x1_h[(size_t)BATCH * 2048];
__device__ bf16 g_x1_l[(size_t)BATCH * 2048];
__device__ bf16 g_x2_h[(size_t)BATCH * 1024];
__device__ bf16 g_x2_l[(size_t)BATCH * 1024];
__device__ bf16 g_x3_h[(size_t)BATCH * 1024];
__device__ bf16 g_x3_l[(size_t)BATCH * 1024];
__device__ bf16 g_x4_h[(size_t)BATCH * 512];
__device__ bf16 g_x4_l[(size_t)BATCH * 512];
// weights in original [Kpad, N] layout, bf16 hi/lo
__device__ bf16 g_w1_h[(size_t)5152 * 2048];
__device__ bf16 g_w1_l[(size_t)5152 * 2048];
__device__ bf16 g_w2_h[(size_t)7200 * 1024];
__device__ bf16 g_w2_l[(size_t)7200 * 1024];
__device__ bf16 g_w3_h[(size_t)6176 * 1024];
__device__ bf16 g_w3_l[(size_t)6176 * 1024];
__device__ bf16 g_w4_h[(size_t)6176 * 512];
__device__ bf16 g_w4_l[(size_t)6176 * 512];
__device__ bf16 g_w5_h[(size_t)512  * 1024];
__device__ bf16 g_w5_l[(size_t)512  * 1024];

// ---------------- PTX helpers ----------------------------------------------
__device__ __forceinline__ uint32_t smem_u32(const void* p) {
    uint32_t a;
    asm("{ .reg .u64 t; cvta.to.shared.u64 t, %1; cvt.u32.u64 %0, t; }"
        : "=r"(a) : "l"(p));
    return a;
}
__device__ __forceinline__ void cp16(uint32_t dst, const void* src) {
    asm volatile("cp.async.cg.shared.global [%0], [%1], 16;" :: "r"(dst), "l"(src));
}
__device__ __forceinline__ void cp_commit() {
    asm volatile("cp.async.commit_group;" ::: "memory");
}
__device__ __forceinline__ void ldsm4(uint32_t* r, uint32_t a) {
    asm volatile("ldmatrix.sync.aligned.m8n8.x4.shared.b16 {%0,%1,%2,%3}, [%4];"
        : "=r"(r[0]), "=r"(r[1]), "=r"(r[2]), "=r"(r[3]) : "r"(a));
}
__device__ __forceinline__ void ldsm4t(uint32_t* r, uint32_t a) {
    asm volatile("ldmatrix.sync.aligned.m8n8.x4.trans.shared.b16 {%0,%1,%2,%3}, [%4];"
        : "=r"(r[0]), "=r"(r[1]), "=r"(r[2]), "=r"(r[3]) : "r"(a));
}
__device__ __forceinline__ void mma16816(float* d, const uint32_t* a, const uint32_t* b) {
    asm volatile(
        "mma.sync.aligned.m16n8k16.row.col.f32.bf16.bf16.f32 "
        "{%0,%1,%2,%3}, {%4,%5,%6,%7}, {%8,%9}, {%0,%1,%2,%3};"
        : "+f"(d[0]), "+f"(d[1]), "+f"(d[2]), "+f"(d[3])
        : "r"(a[0]), "r"(a[1]), "r"(a[2]), "r"(a[3]), "r"(b[0]), "r"(b[1]));
}
__device__ __forceinline__ void split2(float v, bf16& h, bf16& l) {
    h = __float2bfloat16_rn(v);
    l = __float2bfloat16_rn(v - __bfloat162float(h));
}

// ---------------- ctx build: fp32 -> bf16 hi/lo, padded --------------------
__global__ void build_ctx(const float* __restrict__ state,
                          const float* __restrict__ task,
                          const float* __restrict__ action) {
    int r = blockIdx.x, t = threadIdx.x;
    bf16* ch = g_ctx_h + (size_t)r * CTXP;
    bf16* cl = g_ctx_l + (size_t)r * CTXP;

    const float4* s4 = reinterpret_cast<const float4*>(state + (size_t)r * 4096);
    #pragma unroll 2
    for (int i = t; i < 1024; i += 256) {
        float4 v = s4[i];
        bf16 h0,l0,h1,l1,h2,l2,h3,l3;
        split2(v.x,h0,l0); split2(v.y,h1,l1); split2(v.z,h2,l2); split2(v.w,h3,l3);
        *reinterpret_cast<__nv_bfloat162*>(ch + 4*i)     = __nv_bfloat162(h0,h1);
        *reinterpret_cast<__nv_bfloat162*>(ch + 4*i + 2) = __nv_bfloat162(h2,h3);
        *reinterpret_cast<__nv_bfloat162*>(cl + 4*i)     = __nv_bfloat162(l0,l1);
        *reinterpret_cast<__nv_bfloat162*>(cl + 4*i + 2) = __nv_bfloat162(l2,l3);
    }
    if (t < 4) {
        bf16 h,l; split2(task[(size_t)r*4 + t], h, l);
        ch[4096 + t] = h; cl[4096 + t] = l;
    }
    {
        const float4* a4 = reinterpret_cast<const float4*>(action + (size_t)r * 1024);
        float4 v = a4[t];
        bf16 h0,l0,h1,l1,h2,l2,h3,l3;
        split2(v.x,h0,l0); split2(v.y,h1,l1); split2(v.z,h2,l2); split2(v.w,h3,l3);
        int c = 4100 + 4*t;
        *reinterpret_cast<__nv_bfloat162*>(ch + c)     = __nv_bfloat162(h0,h1);
        *reinterpret_cast<__nv_bfloat162*>(ch + c + 2) = __nv_bfloat162(h2,h3);
        *reinterpret_cast<__nv_bfloat162*>(cl + c)     = __nv_bfloat162(l0,l1);
        *reinterpret_cast<__nv_bfloat162*>(cl + c + 2) = __nv_bfloat162(l2,l3);
    }
    if (t < 28) {  // zero pad 5124..5151
        bf16 z = __float2bfloat16_rn(0.0f);
        ch[5124 + t] = z; cl[5124 + t] = z;
    }
}

// ---------------- fused weight split: all 5 weights in one launch ----------
// Padding rows only at the K tail, so element is valid iff idx < Kreal*N.
struct SplitArgs {
    const float* W[5];
    bf16* Wh[5];
    bf16* Wl[5];
    unsigned long long end4[5];    // cumulative end, float4 units
    unsigned long long valid[5];   // Kreal*N per segment (elements)
};

__global__ void split_all(SplitArgs a) {
    unsigned long long e = (unsigned long long)blockIdx.x * 256 + threadIdx.x;
    unsigned long long start = 0;
    #pragma unroll
    for (int s = 0; s < 5; s++) {
        if (e < a.end4[s]) {
            unsigned long long base = (e - start) * 4;
            float4 v = make_float4(0.f, 0.f, 0.f, 0.f);
            if (base < a.valid[s])
                v = *reinterpret_cast<const float4*>(a.W[s] + base);
            bf16 h0,l0,h1,l1,h2,l2,h3,l3;
            split2(v.x,h0,l0); split2(v.y,h1,l1);
            split2(v.z,h2,l2); split2(v.w,h3,l3);
            bf16* Wh = a.Wh[s]; bf16* Wl = a.Wl[s];
            *reinterpret_cast<__nv_bfloat162*>(Wh + base)     = __nv_bfloat162(h0,h1);
            *reinterpret_cast<__nv_bfloat162*>(Wh + base + 2) = __nv_bfloat162(h2,h3);
            *reinterpret_cast<__nv_bfloat162*>(Wl + base)     = __nv_bfloat162(l0,l1);
            *reinterpret_cast<__nv_bfloat162*>(Wl + base + 2) = __nv_bfloat162(l2,l3);
            return;
        }
        start = a.end4[s];
    }
}

// ---------------- HMMA split GEMM, 3-stage pipeline -------------------------
// C[8192, N] = [A1(K1) | A2] @ W + bias.  W in [Ktot, N] bf16 hi/lo.
// CTA 128x128, BK=32, 8 warps (2x4), warp tile 64x32.
// smem per stage: A hi/lo stride 80 (conflict-free ldsm), B hi/lo stride 272.
#define A_STRIDE 80
#define B_STRIDE 272
#define ABUF     (128 * A_STRIDE)          // 10240
#define BBUF     (32 * B_STRIDE)           // 8704
#define ST_AH    0
#define ST_AL    ABUF                      // 10240
#define ST_BH    (2 * ABUF)                // 20480
#define ST_BL    (2 * ABUF + BBUF)         // 29184
#define STAGE_SZ (2 * ABUF + 2 * BBUF)     // 37888
#define NSTAGE   3
#define SMEM_TOT (NSTAGE * STAGE_SZ)       // 113664

__global__ __launch_bounds__(256, 2)
void gemm_hmma_split(const bf16* __restrict__ A1h, const bf16* __restrict__ A1l,
                     int sA1, int K1,
                     const bf16* __restrict__ A2h, const bf16* __restrict__ A2l,
                     int sA2, int Ktot,
                     const bf16* __restrict__ Wh, const bf16* __restrict__ Wl,
                     const float* __restrict__ bias,
                     float* __restrict__ Cf,
                     bf16* __restrict__ Ch, bf16* __restrict__ Cl,
                     int N) {
    extern __shared__ char smem_raw[];
    const uint32_t sb = smem_u32(smem_raw);

    const int tid  = threadIdx.x;
    const int wid  = tid >> 5;
    const int lane = tid & 31;
    const int warp_m = (wid & 1) * 64;
    const int warp_n = (wid >> 1) * 32;
    const int block_row = blockIdx.y * 128;
    const int block_col = blockIdx.x * 128;

    float acc[64];
    #pragma unroll
    for (int i = 0; i < 64; i++) acc[i] = 0.0f;

    const int nk = Ktot >> 5;

    auto load_chunk = [&](int stage, int k0) {
        const bf16 *ah, *al; int st, kk = k0;
        if (k0 < K1) { ah = A1h; al = A1l; st = sA1; }
        else         { ah = A2h; al = A2l; st = sA2; kk = k0 - K1; }
        const uint32_t sbase = sb + stage * STAGE_SZ;
        #pragma unroll
        for (int i = 0; i < 2; i++) {
            int t2 = tid * 2 + i;
            // A: 512 x 16B  (row 0..127, 4 chunks of 8 bf16)
            int ar = t2 >> 2, ac = t2 & 3;
            const char* sh = (const char*)(ah + (size_t)(block_row + ar) * st + kk) + ac * 16;
            const char* sl = (const char*)(al + (size_t)(block_row + ar) * st + kk) + ac * 16;
            uint32_t da = sbase + ST_AH + ar * A_STRIDE + ac * 16;
            cp16(da, sh);
            cp16(da + (ST_AL - ST_AH), sl);
            // B: 512 x 16B  (row 0..31 of k, 16 chunks of 8 bf16 across n)
            int br = t2 >> 4, bc = t2 & 15;
            const char* th = (const char*)(Wh + (size_t)(k0 + br) * N + block_col) + bc * 16;
            const char* tl = (const char*)(Wl + (size_t)(k0 + br) * N + block_col) + bc * 16;
            uint32_t db = sbase + ST_BH + br * B_STRIDE + bc * 16;
            cp16(db, th);
            cp16(db + (ST_BL - ST_BH), tl);
        }
    };

    // prefetch stages 0,1 (always commit so group counting stays uniform)
    load_chunk(0, 0);
    cp_commit();
    if (nk > 1) load_chunk(1, 32);
    cp_commit();

    const int lr = lane & 15;          // ldmatrix row
    const int lc = (lane >> 4) << 3;   // ldmatrix col half

    int stage = 0;
    for (int it = 0; it < nk; ++it) {
        // stage `it` guaranteed complete when <=1 newer group pending
        asm volatile("cp.async.wait_group 1;" ::: "memory");
        __syncthreads();
        // refill buffer (stage+2)%3: its chunk was consumed at iter it-1 and
        // every thread has passed that compute (all are past the sync above).
        if (it + 2 < nk) {
            int s2 = stage + 2;
            if (s2 >= NSTAGE) s2 -= NSTAGE;
            load_chunk(s2, (it + 2) << 5);
        }
        cp_commit();

        const uint32_t sA = sb + stage * STAGE_SZ + ST_AH;
        const uint32_t sB = sb + stage * STAGE_SZ + ST_BH;

        #pragma unroll
        for (int k2 = 0; k2 < 2; k2++) {
            // B fragments: 2x ldmatrix.x4.trans cover n=0..31 (hi and lo)
            uint32_t bh[8], bl[8];
            #pragma unroll
            for (int nb = 0; nb < 2; nb++) {
                uint32_t addr = sB + (k2 * 16 + lr) * B_STRIDE
                              + (warp_n + nb * 16 + lc) * 2;
                ldsm4t(&bh[nb * 4], addr);
                ldsm4t(&bl[nb * 4], addr + (ST_BL - ST_BH));
            }
            #pragma unroll
            for (int mi = 0; mi < 4; mi++) {
                uint32_t ah[4], al[4];
                uint32_t addr = sA + (warp_m + mi * 16 + lr) * A_STRIDE
                              + (k2 * 16 + lc) * 2;
                ldsm4(ah, addr);
                ldsm4(al, addr + (ST_AL - ST_AH));
                #pragma unroll
                for (int ni = 0; ni < 4; ni++) {
                    float* d = acc + (mi * 4 + ni) * 4;
                    const uint32_t* bhf = &bh[ni * 2];
                    const uint32_t* blf = &bl[ni * 2];
                    mma16816(d, ah, bhf);
                    mma16816(d, ah, blf);
                    mma16816(d, al, bhf);
                }
            }
        }
        stage = (stage + 1 == NSTAGE) ? 0 : stage + 1;
    }

    // ---- epilogue: regs -> gmem, +bias ----
    #pragma unroll
    for (int mi = 0; mi < 4; mi++) {
        #pragma unroll
        for (int ni = 0; ni < 4; ni++) {
            const float* d = acc + (mi * 4 + ni) * 4;
            int r0 = block_row + warp_m + mi * 16 + (lane >> 2);
            int c0 = block_col + warp_n + ni * 8 + (lane & 3) * 2;
            float bv0 = bias[c0], bv1 = bias[c0 + 1];
            float v00 = d[0] + bv0, v01 = d[1] + bv1;
            float v10 = d[2] + bv0, v11 = d[3] + bv1;
            if (Cf) {
                *reinterpret_cast<float2*>(Cf + (size_t)r0 * N + c0)       = make_float2(v00, v01);
                *reinterpret_cast<float2*>(Cf + (size_t)(r0 + 8) * N + c0) = make_float2(v10, v11);
            } else {
                bf16 h0,l0,h1,l1;
                split2(v00,h0,l0); split2(v01,h1,l1);
                *reinterpret_cast<__nv_bfloat162*>(Ch + (size_t)r0 * N + c0) = __nv_bfloat162(h0,h1);
                *reinterpret_cast<__nv_bfloat162*>(Cl + (size_t)r0 * N + c0) = __nv_bfloat162(l0,l1);
                split2(v10,h0,l0); split2(v11,h1,l1);
                *reinterpret_cast<__nv_bfloat162*>(Ch + (size_t)(r0+8) * N + c0) = __nv_bfloat162(h0,h1);
                *reinterpret_cast<__nv_bfloat162*>(Cl + (size_t)(r0+8) * N + c0) = __nv_bfloat162(l0,l1);
            }
        }
    }
}

// ---------------- host ------------------------------------------------------
template <typename T>
static T* sym_addr(const void* symbol) {
    void* p = nullptr;
    cudaGetSymbolAddress(&p, symbol);
    return reinterpret_cast<T*>(p);
}

extern "C" void kernel_launch(void* const* d_in, const int* in_sizes, int n_in,
                              void* d_out, int out_size) {
    const float* state  = (const float*)d_in[0];
    const float* action = (const float*)d_in[1];
    const float* task   = (const float*)d_in[2];
    // d_in[3..18]: dead cx branch weights
    const float* W_l1 = (const float*)d_in[19];
    const float* b_l1 = (const float*)d_in[20];
    const float* W_l2 = (const float*)d_in[21];
    const float* b_l2 = (const float*)d_in[22];
    const float* W_l3 = (const float*)d_in[23];
    const float* b_l3 = (const float*)d_in[24];
    const float* W_l4 = (const float*)d_in[25];
    const float* b_l4 = (const float*)d_in[26];
    const float* W_l5 = (const float*)d_in[27];
    const float* b_l5 = (const float*)d_in[28];
    float* out = (float*)d_out;

    static bool attr_set = false;
    if (!attr_set) {
        cudaFuncSetAttribute(gemm_hmma_split,
                             cudaFuncAttributeMaxDynamicSharedMemorySize, SMEM_TOT);
        attr_set = true;
    }

    bf16* ctxh = sym_addr<bf16>(g_ctx_h);
    bf16* ctxl = sym_addr<bf16>(g_ctx_l);
    bf16* x1h = sym_addr<bf16>(g_x1_h);  bf16* x1l = sym_addr<bf16>(g_x1_l);
    bf16* x2h = sym_addr<bf16>(g_x2_h);  bf16* x2l = sym_addr<bf16>(g_x2_l);
    bf16* x3h = sym_addr<bf16>(g_x3_h);  bf16* x3l = sym_addr<bf16>(g_x3_l);
    bf16* x4h = sym_addr<bf16>(g_x4_h);  bf16* x4l = sym_addr<bf16>(g_x4_l);
    bf16* w1h = sym_addr<bf16>(g_w1_h);  bf16* w1l = sym_addr<bf16>(g_w1_l);
    bf16* w2h = sym_addr<bf16>(g_w2_h);  bf16* w2l = sym_addr<bf16>(g_w2_l);
    bf16* w3h = sym_addr<bf16>(g_w3_h);  bf16* w3l = sym_addr<bf16>(g_w3_l);
    bf16* w4h = sym_addr<bf16>(g_w4_h);  bf16* w4l = sym_addr<bf16>(g_w4_l);
    bf16* w5h = sym_addr<bf16>(g_w5_h);  bf16* w5l = sym_addr<bf16>(g_w5_l);

    // launch 0: ctx build
    build_ctx<<<BATCH, 256>>>(state, task, action);

    // launch 1: fused weight split
    SplitArgs sa;
    const unsigned long long sz4[5] = {
        5152ull * 2048 / 4, 7200ull * 1024 / 4, 6176ull * 1024 / 4,
        6176ull * 512 / 4,  512ull * 1024 / 4 };
    const unsigned long long vl[5] = {
        5124ull * 2048, 7172ull * 1024, 6148ull * 1024,
        6148ull * 512,  512ull * 1024 };
    const float* Ws[5] = {W_l1, W_l2, W_l3, W_l4, W_l5};
    bf16* Whs[5] = {w1h, w2h, w3h, w4h, w5h};
    bf16* Wls[5] = {w1l, w2l, w3l, w4l, w5l};
    unsigned long long cum = 0;
    for (int s = 0; s < 5; s++) {
        sa.W[s] = Ws[s]; sa.Wh[s] = Whs[s]; sa.Wl[s] = Wls[s];
        cum += sz4[s]; sa.end4[s] = cum; sa.valid[s] = vl[s];
    }
    split_all<<<(unsigned)((cum + 255) / 256), 256>>>(sa);

    // launches 2..6: the GEMM chain (ncu -s 5 profiles l4)
    gemm_hmma_split<<<dim3(16, 64), 256, SMEM_TOT>>>(
        ctxh, ctxl, CTXP, 5152, nullptr, nullptr, 0, 5152,
        w1h, w1l, b_l1, nullptr, x1h, x1l, 2048);
    gemm_hmma_split<<<dim3(8, 64), 256, SMEM_TOT>>>(
        x1h, x1l, 2048, 2048, ctxh, ctxl, CTXP, 7200,
        w2h, w2l, b_l2, nullptr, x2h, x2l, 1024);
    gemm_hmma_split<<<dim3(8, 64), 256, SMEM_TOT>>>(
        x2h, x2l, 1024, 1024, ctxh, ctxl, CTXP, 6176,
        w3h, w3l, b_l3, nullptr, x3h, x3l, 1024);
    gemm_hmma_split<<<dim3(4, 64), 256, SMEM_TOT>>>(
        x3h, x3l, 1024, 1024, ctxh, ctxl, CTXP, 6176,
        w4h, w4l, b_l4, nullptr, x4h, x4l, 512);
    gemm_hmma_split<<<dim3(8, 64), 256, SMEM_TOT>>>(
        x4h, x4l, 512, 512, nullptr, nullptr, 0, 512,
        w5h, w5l, b_l5, out, nullptr, nullptr, 1024);
}

// round 6
// speedup vs baseline: 2.9765x; 2.9765x over previous
#include <cuda_runtime.h>
#include <cuda_bf16.h>
#include <cstdint>

// ============================================================================
// Policy_Network — collapsed affine form.
// _kwta is identity => whole network is affine:
//   out = [ctx|1] @ E5,  with E1 = [W1; b1],
//   E_{k+1} = E_k @ W_{k+1,a} + [W_{k+1,b}; b_{k+1}]   (a = first n_k rows)
// GEMMs run on the verified R5 bf16 hi/lo split HMMA core (3 MMAs per product,
// err ~2^-18). tcgen05 unavailable (harness targets plain sm_103).
//   comp1: E2[5248,1024] = E1[5248,2048] @ W2a + aug(W2b,b2)
//   comp2: E3[5248,1024] = E2 @ W3a + aug(W3b,b3)
//   comp3: E4[5248, 512] = E3 @ W4a + aug(W4b,b4)
//   comp4: E5[5248,1024] = E4 @ W5  + aug(0,  b5)
//   final: out[8192,1024] = ctx'[8192,5152] @ E5
// ============================================================================

#define BATCH   8192
#define CTXP    5152            // 5124 ctx + 1 bias col + pad to 32
#define MAUG    5248            // 5124 + 1 bias row, padded to 41*128
#define ADDROWS 5124

typedef __nv_bfloat16 bf16;

// ---------------- device scratch (no allocation allowed) -------------------
__device__ bf16 g_ctx_h[(size_t)BATCH * CTXP];
__device__ bf16 g_ctx_l[(size_t)BATCH * CTXP];
__device__ bf16 g_E1_h[(size_t)MAUG * 2048];
__device__ bf16 g_E1_l[(size_t)MAUG * 2048];
__device__ bf16 g_E2_h[(size_t)MAUG * 1024];
__device__ bf16 g_E2_l[(size_t)MAUG * 1024];
__device__ bf16 g_E3_h[(size_t)MAUG * 1024];
__device__ bf16 g_E3_l[(size_t)MAUG * 1024];
__device__ bf16 g_E4_h[(size_t)MAUG * 512];
__device__ bf16 g_E4_l[(size_t)MAUG * 512];
__device__ bf16 g_E5_h[(size_t)MAUG * 1024];
__device__ bf16 g_E5_l[(size_t)MAUG * 1024];
// split "a"-parts of W2..W4 and full W5 (B operands of compositions)
__device__ bf16 g_w2a_h[(size_t)2048 * 1024];
__device__ bf16 g_w2a_l[(size_t)2048 * 1024];
__device__ bf16 g_w3a_h[(size_t)1024 * 1024];
__device__ bf16 g_w3a_l[(size_t)1024 * 1024];
__device__ bf16 g_w4a_h[(size_t)1024 * 512];
__device__ bf16 g_w4a_l[(size_t)1024 * 512];
__device__ bf16 g_w5_h [(size_t)512  * 1024];
__device__ bf16 g_w5_l [(size_t)512  * 1024];

// ---------------- PTX helpers ----------------------------------------------
__device__ __forceinline__ uint32_t smem_u32(const void* p) {
    uint32_t a;
    asm("{ .reg .u64 t; cvta.to.shared.u64 t, %1; cvt.u32.u64 %0, t; }"
        : "=r"(a) : "l"(p));
    return a;
}
__device__ __forceinline__ void cp16(uint32_t dst, const void* src) {
    asm volatile("cp.async.cg.shared.global [%0], [%1], 16;" :: "r"(dst), "l"(src));
}
__device__ __forceinline__ void cp_commit() {
    asm volatile("cp.async.commit_group;" ::: "memory");
}
__device__ __forceinline__ void ldsm4(uint32_t* r, uint32_t a) {
    asm volatile("ldmatrix.sync.aligned.m8n8.x4.shared.b16 {%0,%1,%2,%3}, [%4];"
        : "=r"(r[0]), "=r"(r[1]), "=r"(r[2]), "=r"(r[3]) : "r"(a));
}
__device__ __forceinline__ void ldsm4t(uint32_t* r, uint32_t a) {
    asm volatile("ldmatrix.sync.aligned.m8n8.x4.trans.shared.b16 {%0,%1,%2,%3}, [%4];"
        : "=r"(r[0]), "=r"(r[1]), "=r"(r[2]), "=r"(r[3]) : "r"(a));
}
__device__ __forceinline__ void mma16816(float* d, const uint32_t* a, const uint32_t* b) {
    asm volatile(
        "mma.sync.aligned.m16n8k16.row.col.f32.bf16.bf16.f32 "
        "{%0,%1,%2,%3}, {%4,%5,%6,%7}, {%8,%9}, {%0,%1,%2,%3};"
        : "+f"(d[0]), "+f"(d[1]), "+f"(d[2]), "+f"(d[3])
        : "r"(a[0]), "r"(a[1]), "r"(a[2]), "r"(a[3]), "r"(b[0]), "r"(b[1]));
}
__device__ __forceinline__ void split2(float v, bf16& h, bf16& l) {
    h = __float2bfloat16_rn(v);
    l = __float2bfloat16_rn(v - __bfloat162float(h));
}

// ---------------- ctx build: fp32 -> bf16 hi/lo, bias col = 1 ---------------
__global__ void build_ctx(const float* __restrict__ state,
                          const float* __restrict__ task,
                          const float* __restrict__ action) {
    int r = blockIdx.x, t = threadIdx.x;
    bf16* ch = g_ctx_h + (size_t)r * CTXP;
    bf16* cl = g_ctx_l + (size_t)r * CTXP;

    const float4* s4 = reinterpret_cast<const float4*>(state + (size_t)r * 4096);
    #pragma unroll 2
    for (int i = t; i < 1024; i += 256) {
        float4 v = s4[i];
        bf16 h0,l0,h1,l1,h2,l2,h3,l3;
        split2(v.x,h0,l0); split2(v.y,h1,l1); split2(v.z,h2,l2); split2(v.w,h3,l3);
        *reinterpret_cast<__nv_bfloat162*>(ch + 4*i)     = __nv_bfloat162(h0,h1);
        *reinterpret_cast<__nv_bfloat162*>(ch + 4*i + 2) = __nv_bfloat162(h2,h3);
        *reinterpret_cast<__nv_bfloat162*>(cl + 4*i)     = __nv_bfloat162(l0,l1);
        *reinterpret_cast<__nv_bfloat162*>(cl + 4*i + 2) = __nv_bfloat162(l2,l3);
    }
    if (t < 4) {
        bf16 h,l; split2(task[(size_t)r*4 + t], h, l);
        ch[4096 + t] = h; cl[4096 + t] = l;
    }
    {
        const float4* a4 = reinterpret_cast<const float4*>(action + (size_t)r * 1024);
        float4 v = a4[t];
        bf16 h0,l0,h1,l1,h2,l2,h3,l3;
        split2(v.x,h0,l0); split2(v.y,h1,l1); split2(v.z,h2,l2); split2(v.w,h3,l3);
        int c = 4100 + 4*t;
        *reinterpret_cast<__nv_bfloat162*>(ch + c)     = __nv_bfloat162(h0,h1);
        *reinterpret_cast<__nv_bfloat162*>(ch + c + 2) = __nv_bfloat162(h2,h3);
        *reinterpret_cast<__nv_bfloat162*>(cl + c)     = __nv_bfloat162(l0,l1);
        *reinterpret_cast<__nv_bfloat162*>(cl + c + 2) = __nv_bfloat162(l2,l3);
    }
    if (t == 0) {   // bias column
        ch[5124] = __float2bfloat16_rn(1.0f);
        cl[5124] = __float2bfloat16_rn(0.0f);
    }
    if (t < 27) {   // zero pad 5125..5151
        bf16 z = __float2bfloat16_rn(0.0f);
        ch[5125 + t] = z; cl[5125 + t] = z;
    }
}

// ---------------- E1 = [W1; b1; 0] split ------------------------------------
__global__ void split_aug(const float* __restrict__ W, const float* __restrict__ b,
                          bf16* __restrict__ Eh, bf16* __restrict__ El,
                          int N, size_t total4) {
    size_t e = (size_t)blockIdx.x * 256 + threadIdx.x;
    if (e >= total4) return;
    size_t base = e * 4;
    int r = (int)(base / N);
    int c = (int)(base % N);
    float4 v = make_float4(0.f, 0.f, 0.f, 0.f);
    if (r < ADDROWS)       v = *reinterpret_cast<const float4*>(W + (size_t)r * N + c);
    else if (r == ADDROWS) v = *reinterpret_cast<const float4*>(b + c);
    bf16 h0,l0,h1,l1,h2,l2,h3,l3;
    split2(v.x,h0,l0); split2(v.y,h1,l1); split2(v.z,h2,l2); split2(v.w,h3,l3);
    *reinterpret_cast<__nv_bfloat162*>(Eh + base)     = __nv_bfloat162(h0,h1);
    *reinterpret_cast<__nv_bfloat162*>(Eh + base + 2) = __nv_bfloat162(h2,h3);
    *reinterpret_cast<__nv_bfloat162*>(El + base)     = __nv_bfloat162(l0,l1);
    *reinterpret_cast<__nv_bfloat162*>(El + base + 2) = __nv_bfloat162(l2,l3);
}

// ---------------- fused plain splits (W2a, W3a, W4a, W5) --------------------
struct SplitArgs {
    const float* W[4];
    bf16* Wh[4];
    bf16* Wl[4];
    unsigned long long end4[4];
};

__global__ void split_all(SplitArgs a) {
    unsigned long long e = (unsigned long long)blockIdx.x * 256 + threadIdx.x;
    unsigned long long start = 0;
    #pragma unroll
    for (int s = 0; s < 4; s++) {
        if (e < a.end4[s]) {
            unsigned long long base = (e - start) * 4;
            float4 v = *reinterpret_cast<const float4*>(a.W[s] + base);
            bf16 h0,l0,h1,l1,h2,l2,h3,l3;
            split2(v.x,h0,l0); split2(v.y,h1,l1);
            split2(v.z,h2,l2); split2(v.w,h3,l3);
            bf16* Wh = a.Wh[s]; bf16* Wl = a.Wl[s];
            *reinterpret_cast<__nv_bfloat162*>(Wh + base)     = __nv_bfloat162(h0,h1);
            *reinterpret_cast<__nv_bfloat162*>(Wh + base + 2) = __nv_bfloat162(h2,h3);
            *reinterpret_cast<__nv_bfloat162*>(Wl + base)     = __nv_bfloat162(l0,l1);
            *reinterpret_cast<__nv_bfloat162*>(Wl + base + 2) = __nv_bfloat162(l2,l3);
            return;
        }
        start = a.end4[s];
    }
}

// ---------------- HMMA split GEMM, 3-stage pipeline (verified R5 core) ------
// C[M,N] = A @ W (+ addend).  A row-major [M, lda] bf16 hi/lo; W [Ktot,N].
// CTA 128x128, BK=32, 8 warps (2x4), warp tile 64x32.
#define A_STRIDE 80
#define B_STRIDE 272
#define ABUF     (128 * A_STRIDE)          // 10240
#define BBUF     (32 * B_STRIDE)           // 8704
#define ST_AH    0
#define ST_AL    ABUF
#define ST_BH    (2 * ABUF)
#define ST_BL    (2 * ABUF + BBUF)
#define STAGE_SZ (2 * ABUF + 2 * BBUF)     // 37888
#define NSTAGE   3
#define SMEM_TOT (NSTAGE * STAGE_SZ)       // 113664

__device__ __forceinline__ float addval(const float* AddW, const float* Addb,
                                        int r, int c, int N) {
    if (AddW && r < ADDROWS) return AddW[(size_t)r * N + c];
    if (Addb && r == ADDROWS) return Addb[c];
    return 0.0f;
}

__global__ __launch_bounds__(256, 2)
void gemm_hmma_split(const bf16* __restrict__ Ah, const bf16* __restrict__ Al,
                     int lda, int Ktot,
                     const bf16* __restrict__ Wh, const bf16* __restrict__ Wl,
                     int N,
                     const float* __restrict__ AddW,   // addend rows (pre-offset)
                     const float* __restrict__ Addb,   // addend bias row
                     float* __restrict__ Cf,           // fp32 out (final)
                     bf16* __restrict__ Ch, bf16* __restrict__ Cl) {
    extern __shared__ char smem_raw[];
    const uint32_t sb = smem_u32(smem_raw);

    const int tid  = threadIdx.x;
    const int wid  = tid >> 5;
    const int lane = tid & 31;
    const int warp_m = (wid & 1) * 64;
    const int warp_n = (wid >> 1) * 32;
    const int block_row = blockIdx.y * 128;
    const int block_col = blockIdx.x * 128;

    float acc[64];
    #pragma unroll
    for (int i = 0; i < 64; i++) acc[i] = 0.0f;

    const int nk = Ktot >> 5;

    auto load_chunk = [&](int stage, int k0) {
        const uint32_t sbase = sb + stage * STAGE_SZ;
        #pragma unroll
        for (int i = 0; i < 2; i++) {
            int t2 = tid * 2 + i;
            // A: 512 x 16B  (row 0..127, 4 chunks of 8 bf16)
            int ar = t2 >> 2, ac = t2 & 3;
            const char* sh = (const char*)(Ah + (size_t)(block_row + ar) * lda + k0) + ac * 16;
            const char* sl = (const char*)(Al + (size_t)(block_row + ar) * lda + k0) + ac * 16;
            uint32_t da = sbase + ST_AH + ar * A_STRIDE + ac * 16;
            cp16(da, sh);
            cp16(da + (ST_AL - ST_AH), sl);
            // B: 512 x 16B  (row 0..31 of k, 16 chunks of 8 bf16 across n)
            int br = t2 >> 4, bc = t2 & 15;
            const char* th = (const char*)(Wh + (size_t)(k0 + br) * N + block_col) + bc * 16;
            const char* tl = (const char*)(Wl + (size_t)(k0 + br) * N + block_col) + bc * 16;
            uint32_t db = sbase + ST_BH + br * B_STRIDE + bc * 16;
            cp16(db, th);
            cp16(db + (ST_BL - ST_BH), tl);
        }
    };

    // prefetch stages 0,1 (always commit so group counting stays uniform)
    load_chunk(0, 0);
    cp_commit();
    if (nk > 1) load_chunk(1, 32);
    cp_commit();

    const int lr = lane & 15;          // ldmatrix row
    const int lc = (lane >> 4) << 3;   // ldmatrix col half

    int stage = 0;
    for (int it = 0; it < nk; ++it) {
        asm volatile("cp.async.wait_group 1;" ::: "memory");
        __syncthreads();
        if (it + 2 < nk) {
            int s2 = stage + 2;
            if (s2 >= NSTAGE) s2 -= NSTAGE;
            load_chunk(s2, (it + 2) << 5);
        }
        cp_commit();

        const uint32_t sA = sb + stage * STAGE_SZ + ST_AH;
        const uint32_t sB = sb + stage * STAGE_SZ + ST_BH;

        #pragma unroll
        for (int k2 = 0; k2 < 2; k2++) {
            uint32_t bh[8], bl[8];
            #pragma unroll
            for (int nb = 0; nb < 2; nb++) {
                uint32_t addr = sB + (k2 * 16 + lr) * B_STRIDE
                              + (warp_n + nb * 16 + lc) * 2;
                ldsm4t(&bh[nb * 4], addr);
                ldsm4t(&bl[nb * 4], addr + (ST_BL - ST_BH));
            }
            #pragma unroll
            for (int mi = 0; mi < 4; mi++) {
                uint32_t ah[4], al[4];
                uint32_t addr = sA + (warp_m + mi * 16 + lr) * A_STRIDE
                              + (k2 * 16 + lc) * 2;
                ldsm4(ah, addr);
                ldsm4(al, addr + (ST_AL - ST_AH));
                #pragma unroll
                for (int ni = 0; ni < 4; ni++) {
                    float* d = acc + (mi * 4 + ni) * 4;
                    const uint32_t* bhf = &bh[ni * 2];
                    const uint32_t* blf = &bl[ni * 2];
                    mma16816(d, ah, bhf);
                    mma16816(d, ah, blf);
                    mma16816(d, al, bhf);
                }
            }
        }
        stage = (stage + 1 == NSTAGE) ? 0 : stage + 1;
    }

    // ---- epilogue ----
    #pragma unroll
    for (int mi = 0; mi < 4; mi++) {
        #pragma unroll
        for (int ni = 0; ni < 4; ni++) {
            const float* d = acc + (mi * 4 + ni) * 4;
            int r0 = block_row + warp_m + mi * 16 + (lane >> 2);
            int c0 = block_col + warp_n + ni * 8 + (lane & 3) * 2;
            if (Cf) {
                *reinterpret_cast<float2*>(Cf + (size_t)r0 * N + c0) =
                    make_float2(d[0], d[1]);
                *reinterpret_cast<float2*>(Cf + (size_t)(r0 + 8) * N + c0) =
                    make_float2(d[2], d[3]);
            } else {
                float v00 = d[0] + addval(AddW, Addb, r0,     c0,     N);
                float v01 = d[1] + addval(AddW, Addb, r0,     c0 + 1, N);
                float v10 = d[2] + addval(AddW, Addb, r0 + 8, c0,     N);
                float v11 = d[3] + addval(AddW, Addb, r0 + 8, c0 + 1, N);
                bf16 h0,l0,h1,l1;
                split2(v00,h0,l0); split2(v01,h1,l1);
                *reinterpret_cast<__nv_bfloat162*>(Ch + (size_t)r0 * N + c0) = __nv_bfloat162(h0,h1);
                *reinterpret_cast<__nv_bfloat162*>(Cl + (size_t)r0 * N + c0) = __nv_bfloat162(l0,l1);
                split2(v10,h0,l0); split2(v11,h1,l1);
                *reinterpret_cast<__nv_bfloat162*>(Ch + (size_t)(r0+8) * N + c0) = __nv_bfloat162(h0,h1);
                *reinterpret_cast<__nv_bfloat162*>(Cl + (size_t)(r0+8) * N + c0) = __nv_bfloat162(l0,l1);
            }
        }
    }
}

// ---------------- host ------------------------------------------------------
template <typename T>
static T* sym_addr(const void* symbol) {
    void* p = nullptr;
    cudaGetSymbolAddress(&p, symbol);
    return reinterpret_cast<T*>(p);
}

extern "C" void kernel_launch(void* const* d_in, const int* in_sizes, int n_in,
                              void* d_out, int out_size) {
    const float* state  = (const float*)d_in[0];
    const float* action = (const float*)d_in[1];
    const float* task   = (const float*)d_in[2];
    // d_in[3..18]: dead cx branch weights
    const float* W_l1 = (const float*)d_in[19];
    const float* b_l1 = (const float*)d_in[20];
    const float* W_l2 = (const float*)d_in[21];
    const float* b_l2 = (const float*)d_in[22];
    const float* W_l3 = (const float*)d_in[23];
    const float* b_l3 = (const float*)d_in[24];
    const float* W_l4 = (const float*)d_in[25];
    const float* b_l4 = (const float*)d_in[26];
    const float* W_l5 = (const float*)d_in[27];
    const float* b_l5 = (const float*)d_in[28];
    float* out = (float*)d_out;

    cudaFuncSetAttribute(gemm_hmma_split,
                         cudaFuncAttributeMaxDynamicSharedMemorySize, SMEM_TOT);

    bf16* ctxh = sym_addr<bf16>(g_ctx_h);  bf16* ctxl = sym_addr<bf16>(g_ctx_l);
    bf16* e1h = sym_addr<bf16>(g_E1_h);    bf16* e1l = sym_addr<bf16>(g_E1_l);
    bf16* e2h = sym_addr<bf16>(g_E2_h);    bf16* e2l = sym_addr<bf16>(g_E2_l);
    bf16* e3h = sym_addr<bf16>(g_E3_h);    bf16* e3l = sym_addr<bf16>(g_E3_l);
    bf16* e4h = sym_addr<bf16>(g_E4_h);    bf16* e4l = sym_addr<bf16>(g_E4_l);
    bf16* e5h = sym_addr<bf16>(g_E5_h);    bf16* e5l = sym_addr<bf16>(g_E5_l);
    bf16* w2ah = sym_addr<bf16>(g_w2a_h);  bf16* w2al = sym_addr<bf16>(g_w2a_l);
    bf16* w3ah = sym_addr<bf16>(g_w3a_h);  bf16* w3al = sym_addr<bf16>(g_w3a_l);
    bf16* w4ah = sym_addr<bf16>(g_w4a_h);  bf16* w4al = sym_addr<bf16>(g_w4a_l);
    bf16* w5h  = sym_addr<bf16>(g_w5_h);   bf16* w5l  = sym_addr<bf16>(g_w5_l);

    // 0: ctx build (only needed by final GEMM)
    build_ctx<<<BATCH, 256>>>(state, task, action);

    // 1: E1 = [W1; b1; 0] split
    {
        size_t total4 = (size_t)MAUG * 2048 / 4;
        split_aug<<<(unsigned)((total4 + 255) / 256), 256>>>(
            W_l1, b_l1, e1h, e1l, 2048, total4);
    }

    // 2: fused plain splits of composition B operands
    {
        SplitArgs sa;
        const float* Ws[4] = {W_l2, W_l3, W_l4, W_l5};
        bf16* Whs[4] = {w2ah, w3ah, w4ah, w5h};
        bf16* Wls[4] = {w2al, w3al, w4al, w5l};
        const unsigned long long sz4[4] = {
            2048ull * 1024 / 4, 1024ull * 1024 / 4,
            1024ull * 512 / 4,  512ull * 1024 / 4 };
        unsigned long long cum = 0;
        for (int s = 0; s < 4; s++) {
            sa.W[s] = Ws[s]; sa.Wh[s] = Whs[s]; sa.Wl[s] = Wls[s];
            cum += sz4[s]; sa.end4[s] = cum;
        }
        split_all<<<(unsigned)((cum + 255) / 256), 256>>>(sa);
    }

    // 3..6: weight-chain compositions (M = 5248 = 41*128)
    // E2 = E1 @ W2a + aug(W2 rows 2048.., b2)
    gemm_hmma_split<<<dim3(8, MAUG / 128), 256, SMEM_TOT>>>(
        e1h, e1l, 2048, 2048, w2ah, w2al, 1024,
        W_l2 + (size_t)2048 * 1024, b_l2, nullptr, e2h, e2l);
    // E3 = E2 @ W3a + aug(W3 rows 1024.., b3)
    gemm_hmma_split<<<dim3(8, MAUG / 128), 256, SMEM_TOT>>>(
        e2h, e2l, 1024, 1024, w3ah, w3al, 1024,
        W_l3 + (size_t)1024 * 1024, b_l3, nullptr, e3h, e3l);
    // E4 = E3 @ W4a + aug(W4 rows 1024.., b4)
    gemm_hmma_split<<<dim3(4, MAUG / 128), 256, SMEM_TOT>>>(
        e3h, e3l, 1024, 1024, w4ah, w4al, 512,
        W_l4 + (size_t)1024 * 512, b_l4, nullptr, e4h, e4l);
    // E5 = E4 @ W5 + aug(0, b5)
    gemm_hmma_split<<<dim3(8, MAUG / 128), 256, SMEM_TOT>>>(
        e4h, e4l, 512, 512, w5h, w5l, 1024,
        nullptr, b_l5, nullptr, e5h, e5l);

    // 7: final batch GEMM  out = ctx' @ E5   (bias via augmented column)
    gemm_hmma_split<<<dim3(8, BATCH / 128), 256, SMEM_TOT>>>(
        ctxh, ctxl, CTXP, CTXP, e5h, e5l, 1024,
        nullptr, nullptr, out, nullptr, nullptr);
}

// round 7
// speedup vs baseline: 3.9359x; 1.3223x over previous
#include <cuda_runtime.h>
#include <cuda_bf16.h>
#include <cstdint>

// ============================================================================
// Policy_Network — collapsed affine form + bulk-copy GEMM pipeline.
// out = [ctx|1] @ E5;  E chain composed on-device (R6 math, verified).
// R7: all GEMM operands stored in gmem as exact smem tile images
// (A-chunk = [Ah 10240 | Al 10240], B-chunk = [Bh 8704 | Bl 8704]); the GEMM
// loads each k-chunk with TWO cp.async.bulk ops + mbarrier instead of 2048
// cp.async.16B ops (LDGSTS-issue was ~58% of cycles).
// ============================================================================

#define BATCH   8192
#define CTXK    5152          // final-GEMM K (5125 live + pad)
#define MAUG    5248          // composed-weight rows (5125 + pad), 41*128
#define ADDROWS 5124

typedef __nv_bfloat16 bf16;

// tile image geometry (must match smem layout below)
#define A_STRIDE 80
#define B_STRIDE 272
#define ACH      20480        // A chunk bytes: 128 rows*80 (hi) + same (lo)
#define BCH      17408        // B chunk bytes: 32 rows*272 (hi) + same (lo)
#define AHALF    10240
#define BHALF    8704
#define STAGE_SZ (ACH + BCH)  // 37888
#define NSTAGE   3
#define SMEM_TOT (128 + NSTAGE * STAGE_SZ)

// ---------------- device scratch: operand images ----------------------------
__device__ __align__(16) char g_ctxA [(size_t)64 * 161 * ACH];   // ctx' A-image
__device__ __align__(16) char g_E1A  [(size_t)41 * 64  * ACH];
__device__ __align__(16) char g_E2A  [(size_t)41 * 32  * ACH];
__device__ __align__(16) char g_E3A  [(size_t)41 * 32  * ACH];
__device__ __align__(16) char g_E4A  [(size_t)41 * 16  * ACH];
__device__ __align__(16) char g_W2aB [(size_t)8  * 64  * BCH];
__device__ __align__(16) char g_W3aB [(size_t)8  * 32  * BCH];
__device__ __align__(16) char g_W4aB [(size_t)4  * 32  * BCH];
__device__ __align__(16) char g_W5B  [(size_t)8  * 16  * BCH];
__device__ __align__(16) char g_E5B  [(size_t)8  * 164 * BCH];

// ---------------- PTX helpers ----------------------------------------------
__device__ __forceinline__ uint32_t smem_u32(const void* p) {
    uint32_t a;
    asm("{ .reg .u64 t; cvta.to.shared.u64 t, %1; cvt.u32.u64 %0, t; }"
        : "=r"(a) : "l"(p));
    return a;
}
__device__ __forceinline__ void mbar_init(uint32_t m, uint32_t cnt) {
    asm volatile("mbarrier.init.shared.b64 [%0], %1;" :: "r"(m), "r"(cnt) : "memory");
}
__device__ __forceinline__ void mbar_expect_tx(uint32_t m, uint32_t bytes) {
    asm volatile("mbarrier.arrive.expect_tx.shared.b64 _, [%0], %1;"
                 :: "r"(m), "r"(bytes) : "memory");
}
__device__ __forceinline__ void mbar_wait(uint32_t m, uint32_t parity) {
    asm volatile(
        "{\n\t.reg .pred P;\n\t"
        "W_%=:\n\t"
        "mbarrier.try_wait.parity.acquire.cta.shared::cta.b64 P, [%0], %1, 0x989680;\n\t"
        "@!P bra W_%=;\n\t"
        "}" :: "r"(m), "r"(parity) : "memory");
}
__device__ __forceinline__ void bulk_g2s(uint32_t dst, const void* src,
                                         uint32_t bytes, uint32_t mbar) {
    asm volatile(
        "cp.async.bulk.shared::cta.global.mbarrier::complete_tx::bytes [%0], [%1], %2, [%3];"
        :: "r"(dst), "l"(src), "r"(bytes), "r"(mbar) : "memory");
}
__device__ __forceinline__ void ldsm4(uint32_t* r, uint32_t a) {
    asm volatile("ldmatrix.sync.aligned.m8n8.x4.shared.b16 {%0,%1,%2,%3}, [%4];"
        : "=r"(r[0]), "=r"(r[1]), "=r"(r[2]), "=r"(r[3]) : "r"(a));
}
__device__ __forceinline__ void ldsm4t(uint32_t* r, uint32_t a) {
    asm volatile("ldmatrix.sync.aligned.m8n8.x4.trans.shared.b16 {%0,%1,%2,%3}, [%4];"
        : "=r"(r[0]), "=r"(r[1]), "=r"(r[2]), "=r"(r[3]) : "r"(a));
}
__device__ __forceinline__ void mma16816(float* d, const uint32_t* a, const uint32_t* b) {
    asm volatile(
        "mma.sync.aligned.m16n8k16.row.col.f32.bf16.bf16.f32 "
        "{%0,%1,%2,%3}, {%4,%5,%6,%7}, {%8,%9}, {%0,%1,%2,%3};"
        : "+f"(d[0]), "+f"(d[1]), "+f"(d[2]), "+f"(d[3])
        : "r"(a[0]), "r"(a[1]), "r"(a[2]), "r"(a[3]), "r"(b[0]), "r"(b[1]));
}
__device__ __forceinline__ void split2(float v, bf16& h, bf16& l) {
    h = __float2bfloat16_rn(v);
    l = __float2bfloat16_rn(v - __bfloat162float(h));
}

// image writers: (m,k) into A-image / (k,n) into B-image; k/n pair-aligned even
__device__ __forceinline__ void writeA2(char* img, int nk, int m, int k,
                                        bf16 h0, bf16 h1, bf16 l0, bf16 l1) {
    char* base = img + (size_t)(m >> 7) * ((size_t)nk * ACH)
               + (size_t)(k >> 5) * ACH + (m & 127) * A_STRIDE + (k & 31) * 2;
    *reinterpret_cast<__nv_bfloat162*>(base)         = __nv_bfloat162(h0, h1);
    *reinterpret_cast<__nv_bfloat162*>(base + AHALF) = __nv_bfloat162(l0, l1);
}
__device__ __forceinline__ void writeB2(char* img, int nkB, int k, int n,
                                        bf16 h0, bf16 h1, bf16 l0, bf16 l1) {
    char* base = img + (size_t)(n >> 7) * ((size_t)nkB * BCH)
               + (size_t)(k >> 5) * BCH + (k & 31) * B_STRIDE + (n & 127) * 2;
    *reinterpret_cast<__nv_bfloat162*>(base)         = __nv_bfloat162(h0, h1);
    *reinterpret_cast<__nv_bfloat162*>(base + BHALF) = __nv_bfloat162(l0, l1);
}

// ---------------- ctx' A-image build (k: 0..4095 state, 4096 task, 4100 act,
// 5124 bias=1, 5125..5151 zero) ----------------------------------------------
__global__ void build_ctx(const float* __restrict__ state,
                          const float* __restrict__ task,
                          const float* __restrict__ action) {
    int r = blockIdx.x, t = threadIdx.x;   // 256 threads
    #pragma unroll 2
    for (int i = t; i < 1024; i += 256) {
        float4 v = reinterpret_cast<const float4*>(state + (size_t)r * 4096)[i];
        bf16 h0,l0,h1,l1,h2,l2,h3,l3;
        split2(v.x,h0,l0); split2(v.y,h1,l1); split2(v.z,h2,l2); split2(v.w,h3,l3);
        writeA2(g_ctxA, 161, r, 4*i,     h0, h1, l0, l1);
        writeA2(g_ctxA, 161, r, 4*i + 2, h2, h3, l2, l3);
    }
    if (t == 0) {
        float4 v = *reinterpret_cast<const float4*>(task + (size_t)r * 4);
        bf16 h0,l0,h1,l1,h2,l2,h3,l3;
        split2(v.x,h0,l0); split2(v.y,h1,l1); split2(v.z,h2,l2); split2(v.w,h3,l3);
        writeA2(g_ctxA, 161, r, 4096, h0, h1, l0, l1);
        writeA2(g_ctxA, 161, r, 4098, h2, h3, l2, l3);
    }
    {
        float4 v = reinterpret_cast<const float4*>(action + (size_t)r * 1024)[t];
        bf16 h0,l0,h1,l1,h2,l2,h3,l3;
        split2(v.x,h0,l0); split2(v.y,h1,l1); split2(v.z,h2,l2); split2(v.w,h3,l3);
        int k = 4100 + 4*t;
        writeA2(g_ctxA, 161, r, k,     h0, h1, l0, l1);
        writeA2(g_ctxA, 161, r, k + 2, h2, h3, l2, l3);
    }
    if (t < 14) {   // k = 5124..5151 as 14 pairs
        bf16 z = __float2bfloat16_rn(0.0f);
        bf16 one = __float2bfloat16_rn(1.0f);
        int k = 5124 + 2*t;
        writeA2(g_ctxA, 161, r, k, (t == 0) ? one : z, z, z, z);
    }
}

// ---------------- E1 = [W1; b1; 0] into A-image (nk=64) ---------------------
__global__ void split_aug(const float* __restrict__ W, const float* __restrict__ b) {
    int m = blockIdx.x;          // 0..5247
    int t = threadIdx.x;         // 512 threads, 4 k each
    int k = t * 4;
    float4 v = make_float4(0.f, 0.f, 0.f, 0.f);
    if (m < ADDROWS)       v = *reinterpret_cast<const float4*>(W + (size_t)m * 2048 + k);
    else if (m == ADDROWS) v = *reinterpret_cast<const float4*>(b + k);
    bf16 h0,l0,h1,l1,h2,l2,h3,l3;
    split2(v.x,h0,l0); split2(v.y,h1,l1); split2(v.z,h2,l2); split2(v.w,h3,l3);
    writeA2(g_E1A, 64, m, k,     h0, h1, l0, l1);
    writeA2(g_E1A, 64, m, k + 2, h2, h3, l2, l3);
}

// ---------------- fused weight splits into B-images -------------------------
struct SplitArgs {
    const float* W[4];
    char* img[4];
    int N[4];
    int nkB[4];
    unsigned long long end4[4];
};

__global__ void split_all(SplitArgs a) {
    unsigned long long e = (unsigned long long)blockIdx.x * 256 + threadIdx.x;
    unsigned long long start = 0;
    #pragma unroll
    for (int s = 0; s < 4; s++) {
        if (e < a.end4[s]) {
            unsigned long long base = (e - start) * 4;
            int N = a.N[s];
            int k = (int)(base / N), n = (int)(base % N);
            float4 v = *reinterpret_cast<const float4*>(a.W[s] + base);
            bf16 h0,l0,h1,l1,h2,l2,h3,l3;
            split2(v.x,h0,l0); split2(v.y,h1,l1);
            split2(v.z,h2,l2); split2(v.w,h3,l3);
            writeB2(a.img[s], a.nkB[s], k, n,     h0, h1, l0, l1);
            writeB2(a.img[s], a.nkB[s], k, n + 2, h2, h3, l2, l3);
            return;
        }
        start = a.end4[s];
    }
}

// ---------------- bulk-fed HMMA split GEMM ----------------------------------
// C[M,N] = A @ B (+addend); A/B read from tile images via cp.async.bulk.
__device__ __forceinline__ float addval(const float* AddW, const float* Addb,
                                        int r, int c, int N) {
    if (AddW && r < ADDROWS) return AddW[(size_t)r * N + c];
    if (Addb && r == ADDROWS) return Addb[c];
    return 0.0f;
}

__global__ __launch_bounds__(256, 2)
void gemm_bulk(const char* __restrict__ Aimg, const char* __restrict__ Bimg,
               int nk, int nkB, int N,
               const float* __restrict__ AddW, const float* __restrict__ Addb,
               float* __restrict__ Cf,
               char* __restrict__ outA, int KCo,
               char* __restrict__ outB, int KCb) {
    extern __shared__ char smem_raw[];
    const uint32_t sb = smem_u32(smem_raw);
    const uint32_t stages = sb + 128;

    const int tid  = threadIdx.x;
    const int wid  = tid >> 5;
    const int lane = tid & 31;
    const int warp_m = (wid & 1) * 64;
    const int warp_n = (wid >> 1) * 32;
    const int block_row = blockIdx.y * 128;
    const int block_col = blockIdx.x * 128;

    const char* Abase = Aimg + (size_t)blockIdx.y * ((size_t)nk  * ACH);
    const char* Bbase = Bimg + (size_t)blockIdx.x * ((size_t)nkB * BCH);

    if (tid == 0) {
        mbar_init(sb + 0, 1);
        mbar_init(sb + 8, 1);
        mbar_init(sb + 16, 1);
    }
    __syncthreads();

    if (tid == 0) {
        #pragma unroll
        for (int s = 0; s < NSTAGE; s++) {
            uint32_t mb = sb + s * 8;
            mbar_expect_tx(mb, STAGE_SZ);
            bulk_g2s(stages + s * STAGE_SZ,       Abase + (size_t)s * ACH, ACH, mb);
            bulk_g2s(stages + s * STAGE_SZ + ACH, Bbase + (size_t)s * BCH, BCH, mb);
        }
    }

    float acc[64];
    #pragma unroll
    for (int i = 0; i < 64; i++) acc[i] = 0.0f;

    const int lr = lane & 15;
    const int lc = (lane >> 4) << 3;

    int stage = 0;
    for (int it = 0; it < nk; ++it) {
        mbar_wait(sb + stage * 8, (uint32_t)((it / NSTAGE) & 1));

        const uint32_t sA = stages + stage * STAGE_SZ;
        const uint32_t sB = sA + ACH;

        #pragma unroll
        for (int k2 = 0; k2 < 2; k2++) {
            uint32_t bh[8], bl[8];
            #pragma unroll
            for (int nb = 0; nb < 2; nb++) {
                uint32_t addr = sB + (k2 * 16 + lr) * B_STRIDE
                              + (warp_n + nb * 16 + lc) * 2;
                ldsm4t(&bh[nb * 4], addr);
                ldsm4t(&bl[nb * 4], addr + BHALF);
            }
            #pragma unroll
            for (int mi = 0; mi < 4; mi++) {
                uint32_t ah[4], al[4];
                uint32_t addr = sA + (warp_m + mi * 16 + lr) * A_STRIDE
                              + (k2 * 16 + lc) * 2;
                ldsm4(ah, addr);
                ldsm4(al, addr + AHALF);
                #pragma unroll
                for (int ni = 0; ni < 4; ni++) {
                    float* d = acc + (mi * 4 + ni) * 4;
                    const uint32_t* bhf = &bh[ni * 2];
                    const uint32_t* blf = &bl[ni * 2];
                    mma16816(d, ah, bhf);
                    mma16816(d, ah, blf);
                    mma16816(d, al, bhf);
                }
            }
        }
        __syncthreads();   // all warps done with this buffer
        if (tid == 0 && it + NSTAGE < nk) {
            uint32_t mb = sb + stage * 8;
            mbar_expect_tx(mb, STAGE_SZ);
            bulk_g2s(stages + stage * STAGE_SZ,       Abase + (size_t)(it + NSTAGE) * ACH, ACH, mb);
            bulk_g2s(stages + stage * STAGE_SZ + ACH, Bbase + (size_t)(it + NSTAGE) * BCH, BCH, mb);
        }
        stage = (stage + 1 == NSTAGE) ? 0 : stage + 1;
    }

    // ---- epilogue ----
    #pragma unroll
    for (int mi = 0; mi < 4; mi++) {
        #pragma unroll
        for (int ni = 0; ni < 4; ni++) {
            const float* d = acc + (mi * 4 + ni) * 4;
            int r0 = block_row + warp_m + mi * 16 + (lane >> 2);
            int c0 = block_col + warp_n + ni * 8 + (lane & 3) * 2;
            if (Cf) {
                *reinterpret_cast<float2*>(Cf + (size_t)r0 * N + c0) =
                    make_float2(d[0], d[1]);
                *reinterpret_cast<float2*>(Cf + (size_t)(r0 + 8) * N + c0) =
                    make_float2(d[2], d[3]);
            } else {
                float v00 = d[0] + addval(AddW, Addb, r0,     c0,     N);
                float v01 = d[1] + addval(AddW, Addb, r0,     c0 + 1, N);
                float v10 = d[2] + addval(AddW, Addb, r0 + 8, c0,     N);
                float v11 = d[3] + addval(AddW, Addb, r0 + 8, c0 + 1, N);
                bf16 h0,l0,h1,l1,h2,l2,h3,l3;
                split2(v00,h0,l0); split2(v01,h1,l1);
                split2(v10,h2,l2); split2(v11,h3,l3);
                if (outA) {
                    writeA2(outA, KCo, r0,     c0, h0, h1, l0, l1);
                    writeA2(outA, KCo, r0 + 8, c0, h2, h3, l2, l3);
                } else {
                    writeB2(outB, KCb, r0,     c0, h0, h1, l0, l1);
                    writeB2(outB, KCb, r0 + 8, c0, h2, h3, l2, l3);
                }
            }
        }
    }
}

// ---------------- host ------------------------------------------------------
template <typename T>
static T* sym_addr(const void* symbol) {
    void* p = nullptr;
    cudaGetSymbolAddress(&p, symbol);
    return reinterpret_cast<T*>(p);
}

extern "C" void kernel_launch(void* const* d_in, const int* in_sizes, int n_in,
                              void* d_out, int out_size) {
    const float* state  = (const float*)d_in[0];
    const float* action = (const float*)d_in[1];
    const float* task   = (const float*)d_in[2];
    // d_in[3..18]: dead cx branch weights
    const float* W_l1 = (const float*)d_in[19];
    const float* b_l1 = (const float*)d_in[20];
    const float* W_l2 = (const float*)d_in[21];
    const float* b_l2 = (const float*)d_in[22];
    const float* W_l3 = (const float*)d_in[23];
    const float* b_l3 = (const float*)d_in[24];
    const float* W_l4 = (const float*)d_in[25];
    const float* b_l4 = (const float*)d_in[26];
    const float* W_l5 = (const float*)d_in[27];
    const float* b_l5 = (const float*)d_in[28];
    float* out = (float*)d_out;

    cudaFuncSetAttribute(gemm_bulk,
                         cudaFuncAttributeMaxDynamicSharedMemorySize, SMEM_TOT);

    char* ctxA = sym_addr<char>(g_ctxA);
    char* e1A  = sym_addr<char>(g_E1A);
    char* e2A  = sym_addr<char>(g_E2A);
    char* e3A  = sym_addr<char>(g_E3A);
    char* e4A  = sym_addr<char>(g_E4A);
    char* w2aB = sym_addr<char>(g_W2aB);
    char* w3aB = sym_addr<char>(g_W3aB);
    char* w4aB = sym_addr<char>(g_W4aB);
    char* w5B  = sym_addr<char>(g_W5B);
    char* e5B  = sym_addr<char>(g_E5B);

    // 0: ctx' A-image
    build_ctx<<<BATCH, 256>>>(state, task, action);
    // 1: E1 A-image
    split_aug<<<MAUG, 512>>>(W_l1, b_l1);
    // 2: B-images of W2a, W3a, W4a, W5
    {
        SplitArgs sa;
        const float* Ws[4] = {W_l2, W_l3, W_l4, W_l5};
        char* imgs[4] = {w2aB, w3aB, w4aB, w5B};
        int Ns[4]   = {1024, 1024, 512, 1024};
        int nkBs[4] = {64, 32, 32, 16};
        const unsigned long long sz4[4] = {
            2048ull * 1024 / 4, 1024ull * 1024 / 4,
            1024ull * 512 / 4,  512ull * 1024 / 4 };
        unsigned long long cum = 0;
        for (int s = 0; s < 4; s++) {
            sa.W[s] = Ws[s]; sa.img[s] = imgs[s];
            sa.N[s] = Ns[s]; sa.nkB[s] = nkBs[s];
            cum += sz4[s]; sa.end4[s] = cum;
        }
        split_all<<<(unsigned)((cum + 255) / 256), 256>>>(sa);
    }

    // 3..6: weight-chain compositions (M = 5248)
    gemm_bulk<<<dim3(8, 41), 256, SMEM_TOT>>>(
        e1A, w2aB, 64, 64, 1024,
        W_l2 + (size_t)2048 * 1024, b_l2, nullptr, e2A, 32, nullptr, 0);
    gemm_bulk<<<dim3(8, 41), 256, SMEM_TOT>>>(
        e2A, w3aB, 32, 32, 1024,
        W_l3 + (size_t)1024 * 1024, b_l3, nullptr, e3A, 32, nullptr, 0);
    gemm_bulk<<<dim3(4, 41), 256, SMEM_TOT>>>(
        e3A, w4aB, 32, 32, 512,
        W_l4 + (size_t)1024 * 512, b_l4, nullptr, e4A, 16, nullptr, 0);
    gemm_bulk<<<dim3(8, 41), 256, SMEM_TOT>>>(
        e4A, w5B, 16, 16, 1024,
        nullptr, b_l5, nullptr, nullptr, 0, e5B, 164);

    // 7: final GEMM  out = ctx' @ E5  (bias via augmented column; K=5152)
    gemm_bulk<<<dim3(8, BATCH / 128), 256, SMEM_TOT>>>(
        ctxA, e5B, 161, 164, 1024,
        nullptr, nullptr, out, nullptr, 0, nullptr, 0);
}